// round 5
// baseline (speedup 1.0000x reference)
#include <cuda_runtime.h>
#include <math.h>

#define NBOX 98
#define THREADS 128

__device__ __forceinline__ float sigm(float v) {
    return 1.0f / (1.0f + expf(-v));
}

__global__ __launch_bounds__(THREADS) void yolo_post_kernel(
    const float* __restrict__ x, float* __restrict__ out, int B)
{
    __shared__ float s_x[1470];
    __shared__ unsigned long long skey[128];
    // per-original-index box data
    __shared__ float o_x1[NBOX], o_y1[NBOX], o_x2[NBOX], o_y2[NBOX], o_sc[NBOX];
    __shared__ int   o_lb[NBOX], o_vl[NBOX];
    // per-sorted-position box data
    __shared__ float t_x1[NBOX], t_y1[NBOX], t_x2[NBOX], t_y2[NBOX], t_ar[NBOX], t_sc[NBOX];
    __shared__ int   t_lb[NBOX], t_vl[NBOX];
    // suppression matrix rows (98 bits per row) + final alive mask
    __shared__ unsigned long long s_M0[NBOX], s_M1[NBOX];
    __shared__ unsigned long long s_alive[2];

    const int tid = threadIdx.x;
    const int img = blockIdx.x;
    const float* __restrict__ xin = x + (size_t)img * 1470;

    // ---- stage input row into smem (coalesced) ----
    for (int i = tid; i < 1470; i += THREADS) s_x[i] = xin[i];
    __syncthreads();

    // ---- per-box decode: coords, objectness gate, class argmax/max ----
    unsigned long long key = 0xFFFFFFFFFFFFFFFFull;  // padding sorts to the end
    if (tid < NBOX) {
        const int cell = tid >> 1;
        const int a    = tid & 1;
        const int ci   = cell / 7;   // row  -> c_y = ci*64
        const int cj   = cell % 7;   // col  -> c_x = cj*64
        const int abase = cell * 30 + a * 5;
        const float tx = s_x[abase + 0];
        const float ty = s_x[abase + 1];
        const float tw = s_x[abase + 2];
        const float th = s_x[abase + 3];
        const float to = s_x[abase + 4];

        const int cbase = cell * 30 + 10;
        float best = s_x[cbase];
        int   bl = 0;
        #pragma unroll
        for (int c = 1; c < 20; ++c) {
            float v = s_x[cbase + c];
            if (v > best) { best = v; bl = c; }  // first-max, matches jnp.argmax
        }

        const float bx = sigm(tx) + (float)cj * 64.0f;
        const float by = sigm(ty) + (float)ci * 64.0f;
        const float bw = sigm(tw);
        const float bh = sigm(th);
        const float x1 = fminf(fmaxf(bx, 0.0f), 1.0f);
        const float y1 = fminf(fmaxf(by, 0.0f), 1.0f);
        const float x2 = fminf(fmaxf(bx + bw, 0.0f), 1.0f);
        const float y2 = fminf(fmaxf(by + bh, 0.0f), 1.0f);
        const int valid = (to >= 0.0f);   // sigmoid(to) >= 0.5  <=>  to >= 0

        o_x1[tid] = x1; o_y1[tid] = y1; o_x2[tid] = x2; o_y2[tid] = y2;
        o_sc[tid] = best; o_lb[tid] = bl; o_vl[tid] = valid;

        // sortable key: descending (valid ? score : -inf), stable by index
        const float s = valid ? best : -INFINITY;
        unsigned u  = __float_as_uint(s);
        unsigned ou = (u & 0x80000000u) ? ~u : (u | 0x80000000u);  // total-order map
        key = (((unsigned long long)(~ou)) << 32) | (unsigned)tid;
    }
    skey[tid] = key;
    __syncthreads();

    // ---- bitonic sort of 128 keys, ascending ----
    for (int k = 2; k <= 128; k <<= 1) {
        for (int j = k >> 1; j >= 1; j >>= 1) {
            const unsigned long long av = skey[tid];
            const unsigned long long bv = skey[tid ^ j];
            const bool up    = ((tid & k) == 0);
            const bool lower = ((tid & j) == 0);
            const unsigned long long mn = (av < bv) ? av : bv;
            const unsigned long long mx = (av < bv) ? bv : av;
            const unsigned long long r  = (lower == up) ? mn : mx;
            __syncthreads();
            skey[tid] = r;
            __syncthreads();
        }
    }

    // ---- gather into sorted order ----
    if (tid < NBOX) {
        const int o = (int)(skey[tid] & 0x7Full);
        const float x1 = o_x1[o], y1 = o_y1[o], x2 = o_x2[o], y2 = o_y2[o];
        t_x1[tid] = x1; t_y1[tid] = y1; t_x2[tid] = x2; t_y2[tid] = y2;
        t_ar[tid] = (x2 - x1) * (y2 - y1);
        t_sc[tid] = o_sc[o]; t_lb[tid] = o_lb[o]; t_vl[tid] = o_vl[o];
    }
    __syncthreads();

    // ---- build suppression bitmask rows: M[i] has bit j set iff j>i && iou(i,j)>0.7 ----
    if (tid < NBOX) {
        unsigned long long m0 = 0, m1 = 0;
        const float x1 = t_x1[tid], y1 = t_y1[tid];
        const float x2 = t_x2[tid], y2 = t_y2[tid], ar = t_ar[tid];
        for (int jj = tid + 1; jj < NBOX; ++jj) {
            const float lx = fmaxf(x1, t_x1[jj]);
            const float ly = fmaxf(y1, t_y1[jj]);
            const float rx = fminf(x2, t_x2[jj]);
            const float ry = fminf(y2, t_y2[jj]);
            const float w  = fmaxf(rx - lx, 0.0f);
            const float h  = fmaxf(ry - ly, 0.0f);
            const float inter = w * h;
            const float uni   = ar + t_ar[jj] - inter;
            const float iou   = inter / uni;     // matches reference op order
            if (uni > 0.0f && iou > 0.7f) {
                if (jj < 64) m0 |= 1ull << jj;
                else         m1 |= 1ull << (jj - 64);
            }
        }
        s_M0[tid] = m0; s_M1[tid] = m1;
    }
    __syncthreads();

    // ---- serial greedy scan (exact fori_loop semantics), one thread ----
    if (tid == 0) {
        unsigned long long a0 = 0, a1 = 0;
        for (int r = 0; r < 64; ++r)     if (t_vl[r]) a0 |= 1ull << r;
        for (int r = 64; r < NBOX; ++r)  if (t_vl[r]) a1 |= 1ull << (r - 64);
        for (int i = 0; i < NBOX; ++i) {
            const bool al = (i < 64) ? ((a0 >> i) & 1ull) : ((a1 >> (i - 64)) & 1ull);
            if (al) { a0 &= ~s_M0[i]; a1 &= ~s_M1[i]; }
        }
        s_alive[0] = a0; s_alive[1] = a1;
    }
    __syncthreads();

    // ---- emit: boxes [B,98,4] | scores [B,98] | labels [B,98] | keep [B,98], all f32 ----
    if (tid < NBOX) {
        const bool alive = (tid < 64) ? ((s_alive[0] >> tid) & 1ull)
                                      : ((s_alive[1] >> (tid - 64)) & 1ull);
        const bool keep = alive && (t_sc[tid] >= 0.05f);

        float4 bb = keep ? make_float4(t_x1[tid], t_y1[tid], t_x2[tid], t_y2[tid])
                         : make_float4(0.0f, 0.0f, 0.0f, 0.0f);
        reinterpret_cast<float4*>(out + (size_t)img * (NBOX * 4))[tid] = bb;

        size_t off = (size_t)B * (NBOX * 4);
        out[off + (size_t)img * NBOX + tid] = keep ? t_sc[tid] : 0.0f;
        off += (size_t)B * NBOX;
        out[off + (size_t)img * NBOX + tid] = keep ? (float)t_lb[tid] : 0.0f;
        off += (size_t)B * NBOX;
        out[off + (size_t)img * NBOX + tid] = keep ? 1.0f : 0.0f;
    }
}

extern "C" void kernel_launch(void* const* d_in, const int* in_sizes, int n_in,
                              void* d_out, int out_size)
{
    const float* x = (const float*)d_in[0];
    const int B = in_sizes[0] / 1470;
    yolo_post_kernel<<<B, THREADS>>>(x, (float*)d_out, B);
}

// round 6
// speedup vs baseline: 2.9237x; 2.9237x over previous
#include <cuda_runtime.h>
#include <math.h>

#define NBOX 98
#define THREADS 128

__device__ __forceinline__ float sigm(float v) {
    return 1.0f / (1.0f + __expf(-v));
}

__device__ __forceinline__ unsigned long long shfl_xor64(unsigned long long v, int j) {
    unsigned lo = (unsigned)v;
    unsigned hi = (unsigned)(v >> 32);
    lo = __shfl_xor_sync(0xFFFFFFFFu, lo, j);
    hi = __shfl_xor_sync(0xFFFFFFFFu, hi, j);
    return ((unsigned long long)hi << 32) | lo;
}

__global__ __launch_bounds__(THREADS, 10) void yolo_post_kernel(
    const float* __restrict__ x, float* __restrict__ out, int B)
{
    __shared__ float s_x[1470];
    __shared__ unsigned long long skey[128];          // only for j>=32 sort steps
    __shared__ float4 o_box[NBOX];                    // original-index boxes (xyxy)
    __shared__ float  o_sc[NBOX];
    __shared__ int    o_lb[NBOX];
    __shared__ float4 s_box[NBOX];                    // sorted boxes
    __shared__ float  t_ar[NBOX], t_sc[NBOX];
    __shared__ int    t_lb[NBOX];
    __shared__ unsigned long long s_M0[NBOX], s_M1[NBOX];
    __shared__ unsigned long long s_alive[2];
    __shared__ int s_V;

    const int tid = threadIdx.x;
    const int img = blockIdx.x;
    const float* __restrict__ xin = x + (size_t)img * 1470;

    if (tid == 0) s_V = 0;

    // ---- stage input row (coalesced) ----
    for (int i = tid; i < 1470; i += THREADS) s_x[i] = xin[i];
    __syncthreads();

    // ---- decode: coords, objectness gate, class argmax/max; key in register ----
    unsigned long long key = 0xFFFFFFFFFFFFFFFFull;   // padding sorts last
    bool validf = false;
    if (tid < NBOX) {
        const int cell = tid >> 1;
        const int a    = tid & 1;
        const int ci   = cell / 7;
        const int cj   = cell % 7;
        const int abase = cell * 30 + a * 5;
        const float tx = s_x[abase + 0];
        const float ty = s_x[abase + 1];
        const float tw = s_x[abase + 2];
        const float th = s_x[abase + 3];
        const float to = s_x[abase + 4];

        const int cbase = cell * 30 + 10;
        float best = s_x[cbase];
        int   bl = 0;
        #pragma unroll
        for (int c = 1; c < 20; ++c) {
            float v = s_x[cbase + c];
            if (v > best) { best = v; bl = c; }   // first-max == jnp.argmax
        }

        const float bx = sigm(tx) + (float)cj * 64.0f;
        const float by = sigm(ty) + (float)ci * 64.0f;
        const float bw = sigm(tw);
        const float bh = sigm(th);
        const float x1 = fminf(fmaxf(bx, 0.0f), 1.0f);
        const float y1 = fminf(fmaxf(by, 0.0f), 1.0f);
        const float x2 = fminf(fmaxf(bx + bw, 0.0f), 1.0f);
        const float y2 = fminf(fmaxf(by + bh, 0.0f), 1.0f);
        validf = (to >= 0.0f);                    // sigmoid(to)>=0.5 <=> to>=0

        o_box[tid] = make_float4(x1, y1, x2, y2);
        o_sc[tid] = best; o_lb[tid] = bl;

        const float s = validf ? best : -INFINITY;
        unsigned u  = __float_as_uint(s);
        unsigned ou = (u & 0x80000000u) ? ~u : (u | 0x80000000u);
        key = (((unsigned long long)(~ou)) << 32) | (unsigned)tid;
    }

    // count valid boxes (valid boxes occupy sorted positions [0, V))
    {
        unsigned bal = __ballot_sync(0xFFFFFFFFu, validf);
        if ((tid & 31) == 0) atomicAdd(&s_V, __popc(bal));
    }

    // ---- bitonic sort of 128 keys, ascending; shfl for j<32, smem for j>=32 ----
    unsigned long long v = key;
    #pragma unroll
    for (int k = 2; k <= 128; k <<= 1) {
        #pragma unroll
        for (int j = k >> 1; j >= 1; j >>= 1) {
            unsigned long long o;
            if (j >= 32) {
                skey[tid] = v;
                __syncthreads();
                o = skey[tid ^ j];
                __syncthreads();
            } else {
                o = shfl_xor64(v, j);
            }
            const bool up    = ((tid & k) == 0);
            const bool lower = ((tid & j) == 0);
            const unsigned long long mn = (v < o) ? v : o;
            const unsigned long long mx = (v < o) ? o : v;
            v = (lower == up) ? mn : mx;
        }
    }
    // note: the k=64/k=128 smem steps guarantee barriers after decode writes
    // and after the last atomicAdd, so o_* and s_V are coherent below.

    const int V = s_V;

    // ---- gather into sorted order (own key is in register v) ----
    if (tid < NBOX) {
        const int o = (int)(v & 0x7Full);
        const float4 b = o_box[o];
        s_box[tid] = b;
        t_ar[tid]  = (b.z - b.x) * (b.w - b.y);
        t_sc[tid]  = o_sc[o];
        t_lb[tid]  = o_lb[o];
    }
    __syncthreads();

    // ---- suppression bitmask rows, restricted to valid prefix [0, V) ----
    if (tid < V) {
        unsigned long long m0 = 0, m1 = 0;
        const float4 a = s_box[tid];
        const float ar = t_ar[tid];
        for (int jj = tid + 1; jj < V; ++jj) {
            const float4 c = s_box[jj];
            const float lx = fmaxf(a.x, c.x);
            const float ly = fmaxf(a.y, c.y);
            const float rx = fminf(a.z, c.z);
            const float ry = fminf(a.w, c.w);
            const float w  = fmaxf(rx - lx, 0.0f);
            const float h  = fmaxf(ry - ly, 0.0f);
            const float inter = w * h;
            const float uni   = ar + t_ar[jj] - inter;
            const float iou   = inter / uni;
            if (uni > 0.0f && iou > 0.7f) {
                if (jj < 64) m0 |= 1ull << jj;
                else         m1 |= 1ull << (jj - 64);
            }
        }
        s_M0[tid] = m0; s_M1[tid] = m1;
    }
    __syncthreads();

    // ---- serial greedy NMS scan (exact fori_loop semantics) ----
    if (tid == 0) {
        unsigned long long a0 = (V >= 64) ? ~0ull : ((1ull << V) - 1ull);
        unsigned long long a1 = (V > 64)  ? ((1ull << (V - 64)) - 1ull) : 0ull;
        for (int i = 0; i < V; ++i) {
            const bool al = (i < 64) ? ((a0 >> i) & 1ull) : ((a1 >> (i - 64)) & 1ull);
            if (al) { a0 &= ~s_M0[i]; a1 &= ~s_M1[i]; }
        }
        s_alive[0] = a0; s_alive[1] = a1;
    }
    __syncthreads();

    // ---- emit: boxes [B,98,4] | scores [B,98] | labels [B,98] | keep [B,98] ----
    if (tid < NBOX) {
        const bool alive = (tid < 64) ? ((s_alive[0] >> tid) & 1ull)
                                      : ((s_alive[1] >> (tid - 64)) & 1ull);
        const bool keep = alive && (t_sc[tid] >= 0.05f);

        const float4 b = s_box[tid];
        float4 bb = keep ? b : make_float4(0.0f, 0.0f, 0.0f, 0.0f);
        reinterpret_cast<float4*>(out + (size_t)img * (NBOX * 4))[tid] = bb;

        size_t off = (size_t)B * (NBOX * 4);
        out[off + (size_t)img * NBOX + tid] = keep ? t_sc[tid] : 0.0f;
        off += (size_t)B * NBOX;
        out[off + (size_t)img * NBOX + tid] = keep ? (float)t_lb[tid] : 0.0f;
        off += (size_t)B * NBOX;
        out[off + (size_t)img * NBOX + tid] = keep ? 1.0f : 0.0f;
    }
}

extern "C" void kernel_launch(void* const* d_in, const int* in_sizes, int n_in,
                              void* d_out, int out_size)
{
    const float* x = (const float*)d_in[0];
    const int B = in_sizes[0] / 1470;
    yolo_post_kernel<<<B, THREADS>>>(x, (float*)d_out, B);
}

// round 7
// speedup vs baseline: 5.3349x; 1.8247x over previous
#include <cuda_runtime.h>
#include <math.h>

#define NBOX 98
#define THREADS 128
#define NHELP 30   // helper threads 98..127 take second halves of rows 0..29

__device__ __forceinline__ float sigm(float v) {
    return 1.0f / (1.0f + __expf(-v));
}

__device__ __forceinline__ unsigned long long shfl_xor64(unsigned long long v, int j) {
    unsigned lo = (unsigned)v;
    unsigned hi = (unsigned)(v >> 32);
    lo = __shfl_xor_sync(0xFFFFFFFFu, lo, j);
    hi = __shfl_xor_sync(0xFFFFFFFFu, hi, j);
    return ((unsigned long long)hi << 32) | lo;
}

// Accumulate suppression bits for row (a, ar) over sorted positions [lo, hi).
// Branchless; loop split at 64 so the shift target word is static.
__device__ __forceinline__ void iou_rowmask(
    const float4* __restrict__ s_box, const float* __restrict__ t_ar,
    float4 a, float ar, int lo, int hi,
    unsigned long long& m0, unsigned long long& m1)
{
    const int hi0 = min(hi, 64);
    for (int jj = lo; jj < hi0; ++jj) {
        const float4 c = s_box[jj];
        const float lx = fmaxf(a.x, c.x), ly = fmaxf(a.y, c.y);
        const float rx = fminf(a.z, c.z), ry = fminf(a.w, c.w);
        const float w = fmaxf(rx - lx, 0.0f), h = fmaxf(ry - ly, 0.0f);
        const float inter = w * h;
        const float uni = ar + t_ar[jj] - inter;
        // inter/uni > 0.7 (uni>0)  <=>  inter > 0.7*uni
        const bool sup = (uni > 0.0f) && (inter > 0.7f * uni);
        m0 |= ((unsigned long long)sup) << jj;
    }
    for (int jj = max(lo, 64); jj < hi; ++jj) {
        const float4 c = s_box[jj];
        const float lx = fmaxf(a.x, c.x), ly = fmaxf(a.y, c.y);
        const float rx = fminf(a.z, c.z), ry = fminf(a.w, c.w);
        const float w = fmaxf(rx - lx, 0.0f), h = fmaxf(ry - ly, 0.0f);
        const float inter = w * h;
        const float uni = ar + t_ar[jj] - inter;
        const bool sup = (uni > 0.0f) && (inter > 0.7f * uni);
        m1 |= ((unsigned long long)sup) << (jj - 64);
    }
}

__global__ __launch_bounds__(THREADS, 12) void yolo_post_kernel(
    const float* __restrict__ x, float* __restrict__ out, int B)
{
    __shared__ float s_x[1470];
    __shared__ unsigned long long skey[128];
    __shared__ float4 o_box[NBOX];
    __shared__ float  o_sc[NBOX];
    __shared__ int    o_lb[NBOX];
    __shared__ float4 s_box[NBOX];
    __shared__ float  t_ar[NBOX], t_sc[NBOX];
    __shared__ int    t_lb[NBOX];
    __shared__ unsigned long long s_M0[NBOX], s_M1[NBOX];
    __shared__ unsigned long long s_H0[NHELP], s_H1[NHELP];
    __shared__ unsigned long long s_alive[2];

    const int tid = threadIdx.x;
    const int img = blockIdx.x;
    const float* __restrict__ xin = x + (size_t)img * 1470;

    // ---- stage input row (coalesced, float2: 5880B row is 8B-aligned) ----
    {
        const float2* __restrict__ xin2 = (const float2*)xin;
        float2* __restrict__ sx2 = (float2*)s_x;
        #pragma unroll
        for (int i = tid; i < 735; i += THREADS) sx2[i] = xin2[i];
    }
    __syncthreads();

    // ---- decode: coords, objectness gate, class argmax/max; key in register ----
    unsigned long long key = 0xFFFFFFFFFFFFFFFFull;
    bool validf = false;
    if (tid < NBOX) {
        const int cell = tid >> 1;
        const int a    = tid & 1;
        const int ci   = cell / 7;
        const int cj   = cell % 7;
        const int abase = cell * 30 + a * 5;
        const float tx = s_x[abase + 0];
        const float ty = s_x[abase + 1];
        const float tw = s_x[abase + 2];
        const float th = s_x[abase + 3];
        const float to = s_x[abase + 4];

        // class argmax over 20 (first-max == jnp.argmax); float2 loads (8B aligned)
        const float2* __restrict__ cp = (const float2*)(s_x + cell * 30 + 10);
        float best = -INFINITY;
        int   bl = 0;
        #pragma unroll
        for (int c2 = 0; c2 < 10; ++c2) {
            const float2 v = cp[c2];
            if (v.x > best) { best = v.x; bl = 2 * c2; }
            if (v.y > best) { best = v.y; bl = 2 * c2 + 1; }
        }

        const float bx = sigm(tx) + (float)cj * 64.0f;
        const float by = sigm(ty) + (float)ci * 64.0f;
        const float bw = sigm(tw);
        const float bh = sigm(th);
        const float x1 = fminf(fmaxf(bx, 0.0f), 1.0f);
        const float y1 = fminf(fmaxf(by, 0.0f), 1.0f);
        const float x2 = fminf(fmaxf(bx + bw, 0.0f), 1.0f);
        const float y2 = fminf(fmaxf(by + bh, 0.0f), 1.0f);
        validf = (to >= 0.0f);          // sigmoid(to)>=0.5 <=> to>=0

        o_box[tid] = make_float4(x1, y1, x2, y2);
        o_sc[tid] = best; o_lb[tid] = bl;

        const float s = validf ? best : -INFINITY;
        unsigned u  = __float_as_uint(s);
        unsigned ou = (u & 0x80000000u) ? ~u : (u | 0x80000000u);
        key = (((unsigned long long)(~ou)) << 32) | (unsigned)tid;
    }

    // barrier (also counts valid boxes; valid boxes occupy sorted prefix [0,V))
    const int V = __syncthreads_count(validf);

    // ---- bitonic sort of 128 keys, ascending; shfl for j<32, smem for j>=32 ----
    unsigned long long v = key;
    #pragma unroll
    for (int k = 2; k <= 128; k <<= 1) {
        #pragma unroll
        for (int j = k >> 1; j >= 1; j >>= 1) {
            unsigned long long o;
            if (j >= 32) {
                skey[tid] = v;
                __syncthreads();
                o = skey[tid ^ j];
                __syncthreads();
            } else {
                o = shfl_xor64(v, j);
            }
            const bool up    = ((tid & k) == 0);
            const bool lower = ((tid & j) == 0);
            const unsigned long long mn = (v < o) ? v : o;
            const unsigned long long mx = (v < o) ? o : v;
            v = (lower == up) ? mn : mx;
        }
    }

    // ---- gather into sorted order ----
    if (tid < NBOX) {
        const int o = (int)(v & 0x7Full);
        const float4 b = o_box[o];
        s_box[tid] = b;
        t_ar[tid]  = (b.z - b.x) * (b.w - b.y);
        t_sc[tid]  = o_sc[o];
        t_lb[tid]  = o_lb[o];
    }
    __syncthreads();

    // ---- suppression bitmask rows, restricted to valid prefix [0,V) ----
    if (tid < NBOX) {
        unsigned long long m0 = 0, m1 = 0;
        if (tid < V) {
            const float4 a = s_box[tid];
            const float ar = t_ar[tid];
            const int lo = tid + 1;
            int hi = V;
            if (tid < NHELP) {               // heavy rows: do first half only
                const int len = V - lo;
                if (len > 0) hi = lo + ((len + 1) >> 1);
            }
            iou_rowmask(s_box, t_ar, a, ar, lo, hi, m0, m1);
        }
        s_M0[tid] = m0; s_M1[tid] = m1;
    } else {
        // helper: second half of row r = tid-98 (r < 30)
        const int r = tid - NBOX;
        unsigned long long m0 = 0, m1 = 0;
        if (r < V) {
            const int lo0 = r + 1;
            const int len = V - lo0;
            if (len > 0) {
                const int lo = lo0 + ((len + 1) >> 1);
                const float4 a = s_box[r];
                const float ar = t_ar[r];
                iou_rowmask(s_box, t_ar, a, ar, lo, V, m0, m1);
            }
        }
        s_H0[r] = m0; s_H1[r] = m1;
    }
    __syncthreads();

    // ---- serial greedy NMS scan (exact fori_loop semantics) ----
    if (tid == 0) {
        unsigned long long a0 = (V >= 64) ? ~0ull : ((1ull << V) - 1ull);
        unsigned long long a1 = (V > 64)  ? ((1ull << (V - 64)) - 1ull) : 0ull;
        const int vh = min(V, NHELP);
        for (int i = 0; i < vh; ++i) {
            const bool al = (a0 >> i) & 1ull;
            if (al) { a0 &= ~(s_M0[i] | s_H0[i]); a1 &= ~(s_M1[i] | s_H1[i]); }
        }
        for (int i = vh; i < V; ++i) {
            const bool al = (i < 64) ? ((a0 >> i) & 1ull) : ((a1 >> (i - 64)) & 1ull);
            if (al) { a0 &= ~s_M0[i]; a1 &= ~s_M1[i]; }
        }
        s_alive[0] = a0; s_alive[1] = a1;
    }
    __syncthreads();

    // ---- emit: boxes [B,98,4] | scores [B,98] | labels [B,98] | keep [B,98] ----
    if (tid < NBOX) {
        const bool alive = (tid < 64) ? ((s_alive[0] >> tid) & 1ull)
                                      : ((s_alive[1] >> (tid - 64)) & 1ull);
        const bool keep = alive && (t_sc[tid] >= 0.05f);

        const float4 b = s_box[tid];
        float4 bb = keep ? b : make_float4(0.0f, 0.0f, 0.0f, 0.0f);
        reinterpret_cast<float4*>(out + (size_t)img * (NBOX * 4))[tid] = bb;

        size_t off = (size_t)B * (NBOX * 4);
        out[off + (size_t)img * NBOX + tid] = keep ? t_sc[tid] : 0.0f;
        off += (size_t)B * NBOX;
        out[off + (size_t)img * NBOX + tid] = keep ? (float)t_lb[tid] : 0.0f;
        off += (size_t)B * NBOX;
        out[off + (size_t)img * NBOX + tid] = keep ? 1.0f : 0.0f;
    }
}

extern "C" void kernel_launch(void* const* d_in, const int* in_sizes, int n_in,
                              void* d_out, int out_size)
{
    const float* x = (const float*)d_in[0];
    const int B = in_sizes[0] / 1470;
    yolo_post_kernel<<<B, THREADS>>>(x, (float*)d_out, B);
}

// round 8
// speedup vs baseline: 8.5030x; 1.5938x over previous
#include <cuda_runtime.h>
#include <math.h>

#define NBOX 98
#define THREADS 128

__device__ __forceinline__ float sigm(float v) {
    return 1.0f / (1.0f + __expf(-v));
}

__device__ __forceinline__ unsigned long long shfl_xor64(unsigned long long v, int j) {
    unsigned lo = (unsigned)v;
    unsigned hi = (unsigned)(v >> 32);
    lo = __shfl_xor_sync(0xFFFFFFFFu, lo, j);
    hi = __shfl_xor_sync(0xFFFFFFFFu, hi, j);
    return ((unsigned long long)hi << 32) | lo;
}

__global__ __launch_bounds__(THREADS, 14) void yolo_post_kernel(
    const float* __restrict__ x, float* __restrict__ out, int B)
{
    __shared__ float s_x[1470];
    __shared__ unsigned long long skey[128];   // j>=32 bitonic steps only
    __shared__ float4 o_box[NBOX];             // boxes by original index (xyxy)
    __shared__ float  o_sc[NBOX];
    __shared__ int    o_lb[NBOX];

    const int tid = threadIdx.x;
    const int img = blockIdx.x;
    const float* __restrict__ xin = x + (size_t)img * 1470;

    // ---- stage input row (coalesced float2; 5880B rows are 8B-aligned) ----
    {
        const float2* __restrict__ xin2 = (const float2*)xin;
        float2* __restrict__ sx2 = (float2*)s_x;
        #pragma unroll
        for (int i = tid; i < 735; i += THREADS) sx2[i] = xin2[i];
    }
    __syncthreads();

    // ---- decode: coords, objectness gate, class argmax/max; key in register ----
    unsigned long long key = 0xFFFFFFFFFFFFFFFFull;   // padding sorts last
    bool validf = false;
    if (tid < NBOX) {
        const int cell = tid >> 1;
        const int a    = tid & 1;
        const int ci   = cell / 7;
        const int cj   = cell % 7;
        const int abase = cell * 30 + a * 5;
        const float tx = s_x[abase + 0];
        const float ty = s_x[abase + 1];
        const float tw = s_x[abase + 2];
        const float th = s_x[abase + 3];
        const float to = s_x[abase + 4];

        // class argmax over 20 (first-max == jnp.argmax); float2 loads
        const float2* __restrict__ cp = (const float2*)(s_x + cell * 30 + 10);
        float best = -INFINITY;
        int   bl = 0;
        #pragma unroll
        for (int c2 = 0; c2 < 10; ++c2) {
            const float2 vv = cp[c2];
            if (vv.x > best) { best = vv.x; bl = 2 * c2; }
            if (vv.y > best) { best = vv.y; bl = 2 * c2 + 1; }
        }

        const float bx = sigm(tx) + (float)cj * 64.0f;
        const float by = sigm(ty) + (float)ci * 64.0f;
        const float bw = sigm(tw);
        const float bh = sigm(th);
        const float x1 = fminf(fmaxf(bx, 0.0f), 1.0f);
        const float y1 = fminf(fmaxf(by, 0.0f), 1.0f);
        const float x2 = fminf(fmaxf(bx + bw, 0.0f), 1.0f);
        const float y2 = fminf(fmaxf(by + bh, 0.0f), 1.0f);
        validf = (to >= 0.0f);                 // sigmoid(to)>=0.5 <=> to>=0

        o_box[tid] = make_float4(x1, y1, x2, y2);
        o_sc[tid] = best; o_lb[tid] = bl;

        // key: (valid ? score : -inf) descending, stable by ascending index
        const float s = validf ? best : -INFINITY;
        unsigned u  = __float_as_uint(s);
        unsigned ou = (u & 0x80000000u) ? ~u : (u | 0x80000000u);
        key = (((unsigned long long)(~ou)) << 32) | (unsigned)tid;
    }

    // barrier + count of valid boxes (valid boxes occupy sorted prefix [0,V))
    const int V = __syncthreads_count(validf);

    // ---- bitonic sort of 128 keys, ascending; shfl for j<32, smem for j>=32 ----
    unsigned long long v = key;
    #pragma unroll
    for (int k = 2; k <= 128; k <<= 1) {
        #pragma unroll
        for (int j = k >> 1; j >= 1; j >>= 1) {
            unsigned long long o;
            if (j >= 32) {
                skey[tid] = v;
                __syncthreads();
                o = skey[tid ^ j];
                __syncthreads();
            } else {
                o = shfl_xor64(v, j);
            }
            const bool takeSmall = ((tid & k) == 0) == ((tid & j) == 0);
            v = ((v < o) == takeSmall) ? v : o;
        }
    }
    // (last smem step's trailing barrier orders all o_* writes before reads below)

    // ---- gather own sorted element into registers; NMS via structural theorem ----
    //
    // All boxes outside cell (0,0) are clamped degenerate (zero area) for ANY
    // input, so iou==0 for every pair except (orig0, orig1), which share a
    // score (tie -> orig0 ranks first). Hence the only possible suppression:
    // orig1 suppressed iff orig0 valid && IoU(b0,b1) > 0.7.
    if (tid < NBOX) {
        const int o = (int)(v & 0x7Full);
        const float4 b = o_box[o];
        const float sc = o_sc[o];
        const int   lb = o_lb[o];

        bool keep = (tid < V) && (sc >= 0.05f);
        if (keep && o == 1 && s_x[4] >= 0.0f) {      // s_x[4] = raw obj of orig0
            const float4 b0 = o_box[0];
            const float lx = fmaxf(b0.x, b.x), ly = fmaxf(b0.y, b.y);
            const float rx = fminf(b0.z, b.z), ry = fminf(b0.w, b.w);
            const float w  = fmaxf(rx - lx, 0.0f), h = fmaxf(ry - ly, 0.0f);
            const float inter = w * h;
            const float ar0 = (b0.z - b0.x) * (b0.w - b0.y);
            const float ar1 = (b.z - b.x) * (b.w - b.y);
            const float uni = ar0 + ar1 - inter;
            if (uni > 0.0f && inter > 0.7f * uni) keep = false;
        }

        // ---- emit: boxes [B,98,4] | scores [B,98] | labels [B,98] | keep [B,98] ----
        float4 bb = keep ? b : make_float4(0.0f, 0.0f, 0.0f, 0.0f);
        reinterpret_cast<float4*>(out + (size_t)img * (NBOX * 4))[tid] = bb;

        size_t off = (size_t)B * (NBOX * 4);
        out[off + (size_t)img * NBOX + tid] = keep ? sc : 0.0f;
        off += (size_t)B * NBOX;
        out[off + (size_t)img * NBOX + tid] = keep ? (float)lb : 0.0f;
        off += (size_t)B * NBOX;
        out[off + (size_t)img * NBOX + tid] = keep ? 1.0f : 0.0f;
    }
}

extern "C" void kernel_launch(void* const* d_in, const int* in_sizes, int n_in,
                              void* d_out, int out_size)
{
    const float* x = (const float*)d_in[0];
    const int B = in_sizes[0] / 1470;
    yolo_post_kernel<<<B, THREADS>>>(x, (float*)d_out, B);
}

// round 10
// speedup vs baseline: 13.6492x; 1.6052x over previous
#include <cuda_runtime.h>
#include <math.h>

#define NBOX 98
#define THREADS 128

__device__ __forceinline__ float sigm(float v) {
    return 1.0f / (1.0f + __expf(-v));
}

__global__ __launch_bounds__(THREADS, 16) void yolo_post_kernel(
    const float* __restrict__ x, float* __restrict__ out, int B)
{
    __shared__ float s_x[1470];
    __shared__ unsigned long long s_keys[NBOX];  // compacted valid keys
    __shared__ int s_wcnt[4];

    const int tid = threadIdx.x;
    const int img = blockIdx.x;
    const float* __restrict__ xin = x + (size_t)img * 1470;

    // output slice bases
    const size_t oboxes = (size_t)img * (NBOX * 4);
    const size_t osc = (size_t)B * (NBOX * 4) + (size_t)img * NBOX;
    const size_t olb = osc + (size_t)B * NBOX;
    const size_t okp = olb + (size_t)B * NBOX;

    // ---- zero-fill all outputs (ordered before the scatter by the barriers below) ----
    if (tid < NBOX) {
        reinterpret_cast<float4*>(out + oboxes)[tid] = make_float4(0.f, 0.f, 0.f, 0.f);
        out[osc + tid] = 0.f;
        out[olb + tid] = 0.f;
        out[okp + tid] = 0.f;
    }

    // ---- stage input row (coalesced float2) ----
    {
        const float2* __restrict__ xin2 = (const float2*)xin;
        float2* __restrict__ sx2 = (float2*)s_x;
        #pragma unroll
        for (int i = tid; i < 735; i += THREADS) sx2[i] = xin2[i];
    }
    __syncthreads();

    // ---- decode (all 128 threads run convergent up to the shfl; extras mapped to cell 48) ----
    const int bt   = (tid < NBOX) ? tid : (96 + (tid & 1));
    const int cell = bt >> 1;
    const int a    = bt & 1;
    const int ci   = cell / 7;
    const int cj   = cell % 7;
    const int abase = cell * 30 + a * 5;

    // half-argmax over 10 classes + pair exchange (anchors of a cell share scores)
    float myb = -INFINITY; int mybl = 0;
    {
        const float2* __restrict__ cp = (const float2*)(s_x + cell * 30 + 10) + a * 5;
        const int cb = a * 10;
        #pragma unroll
        for (int c2 = 0; c2 < 5; ++c2) {
            const float2 vv = cp[c2];
            if (vv.x > myb) { myb = vv.x; mybl = cb + 2 * c2; }
            if (vv.y > myb) { myb = vv.y; mybl = cb + 2 * c2 + 1; }
        }
    }
    const float ob  = __shfl_xor_sync(0xFFFFFFFFu, myb, 1);
    const int   obl = __shfl_xor_sync(0xFFFFFFFFu, mybl, 1);
    const float lowb  = a ? ob  : myb;  const int lowl  = a ? obl  : mybl;
    const float highb = a ? myb : ob;   const int highl = a ? mybl : obl;
    const float best = (lowb >= highb) ? lowb : highb;   // first-max == jnp.argmax
    const int   bl   = (lowb >= highb) ? lowl : highl;

    const float to = s_x[abase + 4];
    const bool validf = (tid < NBOX) && (to >= 0.0f);  // sigmoid(to)>=0.5 <=> to>=0

    // coords: cells with cj>=1 have x1=x2=1 identically (clamp after +64*cj); same for ci in y
    float x1, x2, y1, y2;
    if (cj == 0) {
        const float sx_ = sigm(s_x[abase + 0]);            // clip(sigm,0,1) == sigm
        x1 = sx_; x2 = fminf(sx_ + sigm(s_x[abase + 2]), 1.0f);
    } else { x1 = 1.0f; x2 = 1.0f; }
    if (ci == 0) {
        const float sy_ = sigm(s_x[abase + 1]);
        y1 = sy_; y2 = fminf(sy_ + sigm(s_x[abase + 3]), 1.0f);
    } else { y1 = 1.0f; y2 = 1.0f; }

    // ---- compact valid keys into s_keys[0..V) in tid order ----
    const unsigned bal = __ballot_sync(0xFFFFFFFFu, validf);
    const int lane = tid & 31, w = tid >> 5;
    if (lane == 0) s_wcnt[w] = __popc(bal);
    const int within = __popc(bal & ((1u << lane) - 1u));
    __syncthreads();
    const int c0 = s_wcnt[0], c1 = s_wcnt[1], c2s = s_wcnt[2], c3 = s_wcnt[3];
    const int V = c0 + c1 + c2s + c3;
    int base = 0;
    if (w > 0) base += c0;
    if (w > 1) base += c1;
    if (w > 2) base += c2s;

    unsigned long long key = 0;
    if (validf) {
        // key: score descending, ties by ascending original index (stable argsort(-s))
        const unsigned u  = __float_as_uint(best);
        const unsigned ou = (u & 0x80000000u) ? ~u : (u | 0x80000000u);
        key = (((unsigned long long)(~ou)) << 32) | (unsigned)tid;
        s_keys[base + within] = key;
    }
    __syncthreads();

    // ---- rank (= sorted position) + NMS theorem + scatter ----
    if (validf) {
        int rank = 0;
        #pragma unroll 4
        for (int j = 0; j < V; ++j)
            rank += (s_keys[j] < key) ? 1 : 0;

        bool keep = (best >= 0.05f);
        // Only possible suppression in the entire 98-box NMS: orig index 1 by orig
        // index 0 (all other boxes are clamp-degenerate with zero area for any
        // input; orig0/orig1 share a score so orig0 ranks first and is never
        // suppressible). s_x[4] is orig0's raw objectness.
        if (keep && bt == 1 && s_x[4] >= 0.0f) {
            const float a0x1 = sigm(s_x[0]);
            const float a0x2 = fminf(a0x1 + sigm(s_x[2]), 1.0f);
            const float a0y1 = sigm(s_x[1]);
            const float a0y2 = fminf(a0y1 + sigm(s_x[3]), 1.0f);
            const float lx = fmaxf(a0x1, x1), ly = fmaxf(a0y1, y1);
            const float rx = fminf(a0x2, x2), ry = fminf(a0y2, y2);
            const float wn = fmaxf(rx - lx, 0.0f), hn = fmaxf(ry - ly, 0.0f);
            const float inter = wn * hn;
            const float uni = (a0x2 - a0x1) * (a0y2 - a0y1)
                            + (x2 - x1) * (y2 - y1) - inter;
            if (uni > 0.0f && inter > 0.7f * uni) keep = false;
        }

        if (keep) {
            reinterpret_cast<float4*>(out + oboxes)[rank] = make_float4(x1, y1, x2, y2);
            out[osc + rank] = best;
            out[olb + rank] = (float)bl;
            out[okp + rank] = 1.0f;
        }
    }
}

extern "C" void kernel_launch(void* const* d_in, const int* in_sizes, int n_in,
                              void* d_out, int out_size)
{
    const float* x = (const float*)d_in[0];
    const int B = in_sizes[0] / 1470;
    yolo_post_kernel<<<B, THREADS>>>(x, (float*)d_out, B);
}

// round 12
// speedup vs baseline: 13.7819x; 1.0097x over previous
#include <cuda_runtime.h>
#include <math.h>

#define NBOX 98
#define THREADS 128

__device__ __forceinline__ float sigm(float v) {
    return 1.0f / (1.0f + __expf(-v));
}

__global__ __launch_bounds__(THREADS, 16) void yolo_post_kernel(
    const float* __restrict__ x, float* __restrict__ out, int B)
{
    __shared__ float s_x[1470];
    __shared__ unsigned long long s_keys[128];  // per-warp segments: warp w -> [32w, 32w+cnt_w)
    __shared__ int s_wcnt[4];

    const int tid = threadIdx.x;
    const int img = blockIdx.x;
    const float* __restrict__ xin = x + (size_t)img * 1470;

    // output slice bases
    const size_t oboxes = (size_t)img * (NBOX * 4);
    const size_t osc = (size_t)B * (NBOX * 4) + (size_t)img * NBOX;
    const size_t olb = osc + (size_t)B * NBOX;
    const size_t okp = olb + (size_t)B * NBOX;

    // ---- stage input row (coalesced float2) ----
    {
        const float2* __restrict__ xin2 = (const float2*)xin;
        float2* __restrict__ sx2 = (float2*)s_x;
        #pragma unroll
        for (int i = tid; i < 735; i += THREADS) sx2[i] = xin2[i];
    }
    __syncthreads();

    // ---- decode (convergent; threads >=98 mapped to cell 48, results unused) ----
    const int bt   = (tid < NBOX) ? tid : (96 + (tid & 1));
    const int cell = bt >> 1;
    const int a    = bt & 1;
    const int ci   = cell / 7;
    const int cj   = cell % 7;
    const int abase = cell * 30 + a * 5;

    // half-argmax over 10 classes + pair merge (anchors share class scores)
    float myb = -INFINITY; int mybl = 0;
    {
        const float2* __restrict__ cp = (const float2*)(s_x + cell * 30 + 10) + a * 5;
        const int cb = a * 10;
        #pragma unroll
        for (int c2 = 0; c2 < 5; ++c2) {
            const float2 vv = cp[c2];
            if (vv.x > myb) { myb = vv.x; mybl = cb + 2 * c2; }
            if (vv.y > myb) { myb = vv.y; mybl = cb + 2 * c2 + 1; }
        }
    }
    const float ob  = __shfl_xor_sync(0xFFFFFFFFu, myb, 1);
    const int   obl = __shfl_xor_sync(0xFFFFFFFFu, mybl, 1);
    const float lowb  = a ? ob  : myb;  const int lowl  = a ? obl  : mybl;
    const float highb = a ? myb : ob;   const int highl = a ? mybl : obl;
    const float best = (lowb >= highb) ? lowb : highb;   // first-max == jnp.argmax
    const int   bl   = (lowb >= highb) ? lowl : highl;

    const float to = s_x[abase + 4];
    const bool validf = (tid < NBOX) && (to >= 0.0f);    // sigmoid(to)>=0.5 <=> to>=0

    // coords: cj>=1 forces x1=x2=1 identically (clamp after +64*cj); same for ci in y
    float x1, x2, y1, y2;
    if (cj == 0) {
        const float sx_ = sigm(s_x[abase + 0]);
        x1 = sx_; x2 = fminf(sx_ + sigm(s_x[abase + 2]), 1.0f);
    } else { x1 = 1.0f; x2 = 1.0f; }
    if (ci == 0) {
        const float sy_ = sigm(s_x[abase + 1]);
        y1 = sy_; y2 = fminf(sy_ + sigm(s_x[abase + 3]), 1.0f);
    } else { y1 = 1.0f; y2 = 1.0f; }

    // ---- compact valid keys into per-warp segments (order within segment irrelevant) ----
    const unsigned bal = __ballot_sync(0xFFFFFFFFu, validf);
    const int lane = tid & 31, w = tid >> 5;
    if (lane == 0) s_wcnt[w] = __popc(bal);
    const int within = __popc(bal & ((1u << lane) - 1u));

    // pair tie-key: (score desc, idx asc), idx pinned to 2*cell for BOTH anchors
    unsigned long long K;
    {
        const unsigned u  = __float_as_uint(best);
        const unsigned ou = (u & 0x80000000u) ? ~u : (u | 0x80000000u);
        K = (((unsigned long long)(~ou)) << 32) | (unsigned)(2 * cell);
    }
    if (validf) {
        // this thread's true key (its own index as tie-break)
        s_keys[w * 32 + within] = K + (unsigned)a;
    }
    __syncthreads();

    const int c0 = s_wcnt[0], c1 = s_wcnt[1], c2s = s_wcnt[2], c3 = s_wcnt[3];
    const int V = c0 + c1 + c2s + c3;

    // ---- pair-split rank: both pair threads count half the keys (strictly < K) ----
    int rk = 0;
    {
        const int cnts[4] = {c0, c1, c2s, c3};
        #pragma unroll
        for (int ww = 0; ww < 4; ++ww) {
            const unsigned long long* seg = s_keys + ww * 32;
            for (int j = a; j < cnts[ww]; j += 2)
                rk += (seg[j] < K) ? 1 : 0;
        }
    }
    rk += __shfl_xor_sync(0xFFFFFFFFu, rk, 1);           // rank of a0
    const unsigned pv0 = (bal >> (lane & ~1)) & 1u;      // pair's a0 validity
    const int rank = rk + (a ? (int)pv0 : 0);

    // ---- emit exactly once per output position ----
    if (tid < NBOX) {
        bool keep = false;
        int pos;
        if (validf) {
            pos = rank;
            keep = (best >= 0.05f);
            // Structural NMS: only orig idx 1 can ever be suppressed (by orig 0);
            // all boxes outside cell(0,0) are clamp-degenerate for any input,
            // and orig0/orig1 share a score so orig0 ranks first.
            if (keep && bt == 1 && s_x[4] >= 0.0f) {
                const float a0x1 = sigm(s_x[0]);
                const float a0x2 = fminf(a0x1 + sigm(s_x[2]), 1.0f);
                const float a0y1 = sigm(s_x[1]);
                const float a0y2 = fminf(a0y1 + sigm(s_x[3]), 1.0f);
                const float lx = fmaxf(a0x1, x1), ly = fmaxf(a0y1, y1);
                const float rx = fminf(a0x2, x2), ry = fminf(a0y2, y2);
                const float wn = fmaxf(rx - lx, 0.0f), hn = fmaxf(ry - ly, 0.0f);
                const float inter = wn * hn;
                const float uni = (a0x2 - a0x1) * (a0y2 - a0y1)
                                + (x2 - x1) * (y2 - y1) - inter;
                if (uni > 0.0f && inter > 0.7f * uni) keep = false;
            }
        } else {
            // tail slot: V + index among invalid boxes (warp-segmented, any order ok
            // as long as it is a bijection onto [V, 98))
            const unsigned boxmask = (w < 3) ? 0xFFFFFFFFu : 0x3u;
            const unsigned invm = boxmask & ~bal;
            int invbase = 0;
            if (w > 0) invbase += 32 - c0;
            if (w > 1) invbase += 32 - c1;
            if (w > 2) invbase += 32 - c2s;
            pos = V + invbase + __popc(invm & ((1u << lane) - 1u));
        }

        const float4 bb = keep ? make_float4(x1, y1, x2, y2)
                               : make_float4(0.f, 0.f, 0.f, 0.f);
        reinterpret_cast<float4*>(out + oboxes)[pos] = bb;
        out[osc + pos] = keep ? best : 0.f;
        out[olb + pos] = keep ? (float)bl : 0.f;
        out[okp + pos] = keep ? 1.f : 0.f;
    }
}

extern "C" void kernel_launch(void* const* d_in, const int* in_sizes, int n_in,
                              void* d_out, int out_size)
{
    const float* x = (const float*)d_in[0];
    const int B = in_sizes[0] / 1470;
    yolo_post_kernel<<<B, THREADS>>>(x, (float*)d_out, B);
}

// round 13
// speedup vs baseline: 15.1496x; 1.0992x over previous
#include <cuda_runtime.h>
#include <math.h>

#define NBOX 98
#define NPAIR 49
#define THREADS 128

__device__ __forceinline__ float sigm(float v) {
    return 1.0f / (1.0f + __expf(-v));
}

__global__ __launch_bounds__(THREADS, 16) void yolo_post_kernel(
    const float* __restrict__ x, float* __restrict__ out, int B)
{
    __shared__ float s_x[1470];
    __shared__ unsigned long long s_pair[NPAIR];  // (score_desc<<32)|(2*cell<<2)|cnt
    __shared__ int s_wcnt[4];

    const int tid = threadIdx.x;
    const int img = blockIdx.x;
    const float* __restrict__ xin = x + (size_t)img * 1470;

    const size_t oboxes = (size_t)img * (NBOX * 4);
    const size_t osc = (size_t)B * (NBOX * 4) + (size_t)img * NBOX;
    const size_t olb = osc + (size_t)B * NBOX;
    const size_t okp = olb + (size_t)B * NBOX;

    // ---- stage input row (coalesced float2, statically unrolled) ----
    {
        const float2* __restrict__ xin2 = (const float2*)xin;
        float2* __restrict__ sx2 = (float2*)s_x;
        #pragma unroll
        for (int it = 0; it < 6; ++it) {
            const int i = tid + it * THREADS;
            if (i < 735) sx2[i] = xin2[i];
        }
    }
    __syncthreads();

    // ---- decode (convergent; threads >=98 mapped to cell 48, results unused) ----
    const int bt   = (tid < NBOX) ? tid : (96 + (tid & 1));
    const int cell = bt >> 1;
    const int a    = bt & 1;
    const int ci   = cell / 7;
    const int cj   = cell % 7;
    const int abase = cell * 30 + a * 5;

    // half-argmax over 10 classes + pair merge (anchors share class scores)
    float myb = -INFINITY; int mybl = 0;
    {
        const float2* __restrict__ cp = (const float2*)(s_x + cell * 30 + 10) + a * 5;
        const int cb = a * 10;
        #pragma unroll
        for (int c2 = 0; c2 < 5; ++c2) {
            const float2 vv = cp[c2];
            if (vv.x > myb) { myb = vv.x; mybl = cb + 2 * c2; }
            if (vv.y > myb) { myb = vv.y; mybl = cb + 2 * c2 + 1; }
        }
    }
    const float ob  = __shfl_xor_sync(0xFFFFFFFFu, myb, 1);
    const int   obl = __shfl_xor_sync(0xFFFFFFFFu, mybl, 1);
    const float lowb  = a ? ob  : myb;  const int lowl  = a ? obl  : mybl;
    const float highb = a ? myb : ob;   const int highl = a ? mybl : obl;
    const float best = (lowb >= highb) ? lowb : highb;   // first-max == jnp.argmax
    const int   bl   = (lowb >= highb) ? lowl : highl;

    const float to = s_x[abase + 4];
    const bool validf = (tid < NBOX) && (to >= 0.0f);    // sigmoid(to)>=0.5 <=> to>=0

    // coords: cj>=1 forces x1=x2=1 identically (clamp after +64*cj); same for ci in y
    float x1, x2, y1, y2;
    if (cj == 0) {
        const float sx_ = sigm(s_x[abase + 0]);
        x1 = sx_; x2 = fminf(sx_ + sigm(s_x[abase + 2]), 1.0f);
    } else { x1 = 1.0f; x2 = 1.0f; }
    if (ci == 0) {
        const float sy_ = sigm(s_x[abase + 1]);
        y1 = sy_; y2 = fminf(sy_ + sigm(s_x[abase + 3]), 1.0f);
    } else { y1 = 1.0f; y2 = 1.0f; }

    // ---- per-pair key entry (one write per pair, by the even-anchor thread) ----
    const unsigned bal = __ballot_sync(0xFFFFFFFFu, validf);
    const int lane = tid & 31, w = tid >> 5;
    if (lane == 0) s_wcnt[w] = __popc(bal);

    // probe key: score descending, then cell index ascending; cnt bits below
    unsigned long long Kme;
    {
        const unsigned u  = __float_as_uint(best);
        const unsigned ou = (u & 0x80000000u) ? ~u : (u | 0x80000000u);
        Kme = (((unsigned long long)(~ou)) << 32) | (unsigned)((2 * cell) << 2);
    }
    const unsigned vother = (bal >> (lane ^ 1)) & 1u;
    if (tid < NBOX && a == 0) {
        const unsigned cnt = (unsigned)validf + vother;
        s_pair[cell] = Kme | cnt;
    }

    // barrier + valid count (valid boxes occupy sorted prefix [0,V))
    const int V = __syncthreads_count(validf);

    // ---- rank: parity-split static scan over 49 pair entries ----
    // rank(pair leader) = sum of cnt over pairs with strictly smaller key.
    // Own entry has equal key-part and cnt>=0 => >= Kme, self-excluded.
    int rk = 0;
    #pragma unroll
    for (int it = 0; it < 25; ++it) {
        const int p = a + 2 * it;
        if (p < NPAIR) {
            const unsigned long long e = s_pair[p];
            if (e < Kme) rk += (int)(e & 3u);
        }
    }
    rk += __shfl_xor_sync(0xFFFFFFFFu, rk, 1);           // full pair-leader rank
    const unsigned pv0 = (bal >> (lane & ~1)) & 1u;      // validity of pair's anchor 0
    const int rank = rk + (a ? (int)pv0 : 0);

    // ---- emit exactly once per output position ----
    if (tid < NBOX) {
        bool keep = false;
        int pos;
        if (validf) {
            pos = rank;
            keep = (best >= 0.05f);
            // Structural NMS: every box outside cell(0,0) is clamp-degenerate
            // (zero area) for any input => iou==0; orig0/orig1 share a score so
            // orig0 ranks first and is unsuppressible. Only check: orig1 vs orig0.
            if (keep && bt == 1 && s_x[4] >= 0.0f) {
                const float a0x1 = sigm(s_x[0]);
                const float a0x2 = fminf(a0x1 + sigm(s_x[2]), 1.0f);
                const float a0y1 = sigm(s_x[1]);
                const float a0y2 = fminf(a0y1 + sigm(s_x[3]), 1.0f);
                const float lx = fmaxf(a0x1, x1), ly = fmaxf(a0y1, y1);
                const float rx = fminf(a0x2, x2), ry = fminf(a0y2, y2);
                const float wn = fmaxf(rx - lx, 0.0f), hn = fmaxf(ry - ly, 0.0f);
                const float inter = wn * hn;
                const float uni = (a0x2 - a0x1) * (a0y2 - a0y1)
                                + (x2 - x1) * (y2 - y1) - inter;
                if (uni > 0.0f && inter > 0.7f * uni) keep = false;
            }
        } else {
            // tail slot: V + rank among invalid boxes by original index
            int nvb = __popc(bal & ((1u << lane) - 1u));
            if (w > 0) nvb += s_wcnt[0];
            if (w > 1) nvb += s_wcnt[1];
            if (w > 2) nvb += s_wcnt[2];
            pos = V + (bt - nvb);
        }

        const float4 bb = keep ? make_float4(x1, y1, x2, y2)
                               : make_float4(0.f, 0.f, 0.f, 0.f);
        reinterpret_cast<float4*>(out + oboxes)[pos] = bb;
        out[osc + pos] = keep ? best : 0.f;
        out[olb + pos] = keep ? (float)bl : 0.f;
        out[okp + pos] = keep ? 1.f : 0.f;
    }
}

extern "C" void kernel_launch(void* const* d_in, const int* in_sizes, int n_in,
                              void* d_out, int out_size)
{
    const float* x = (const float*)d_in[0];
    const int B = in_sizes[0] / 1470;
    yolo_post_kernel<<<B, THREADS>>>(x, (float*)d_out, B);
}